// round 9
// baseline (speedup 1.0000x reference)
#include <cuda_runtime.h>
#include <cuda_fp16.h>
#include <cstdint>
#include <cstddef>

// Problem constants: B=4, S=4096 -> N=16384 tokens
#define N_TOK 16384
#define DIM   4096
#define OUT_D 4096
#define SCALING 0.5f
#define W1_N8 18   // 144 rows / 8: 16 A-blocks + router-hi + router-lo

// -------- static scratch, fp16 fragment-major (m16n8k16) --------
// GEMM1 B operand, interleaved per k32: [k32 0..127][n8 0..17][lane][4]
//   word = lane*4 + ks16*2 + reg, lane=(n&7)*4+((k&7)>>1), reg=(k>>3)&1, ks16=(k>>4)&1
__device__ __align__(16) uint32_t g_w1f[128 * W1_N8 * 128];
// GEMM2 B operand: [n8 0..511][k16 0..7][lane*2 + reg]
__device__ __align__(16) uint32_t g_btf[512 * 8 * 64];
// GEMM2 A operand: [m16 0..1023][k16 0..7][lane*4 + reg]
__device__ __align__(16) uint32_t g_hwf[(size_t)1024 * 8 * 128];

// -------- helpers --------
__device__ __forceinline__ uint32_t pack_f16x2(float lo, float hi) {
    uint32_t r;   // d.low = 2nd src, d.high = 1st src
    asm("cvt.rn.f16x2.f32 %0, %1, %2;" : "=r"(r) : "f"(hi), "f"(lo));
    return r;
}
__device__ __forceinline__ float2 unpack_f16x2(uint32_t v) {
    __half2 h = *(__half2*)&v;
    return __half22float2(h);
}
__device__ __forceinline__ void mma_f16(float* c, const uint32_t* a,
                                        uint32_t b0, uint32_t b1) {
    asm volatile(
        "mma.sync.aligned.m16n8k16.row.col.f32.f16.f16.f32 "
        "{%0,%1,%2,%3}, {%4,%5,%6,%7}, {%8,%9}, {%0,%1,%2,%3};\n"
        : "+f"(c[0]), "+f"(c[1]), "+f"(c[2]), "+f"(c[3])
        : "r"(a[0]), "r"(a[1]), "r"(a[2]), "r"(a[3]), "r"(b0), "r"(b1));
}
__device__ __forceinline__ void cp16(void* dst, const void* src) {
    uint32_t d = (uint32_t)__cvta_generic_to_shared(dst);
    asm volatile("cp.async.cg.shared.global [%0], [%1], 16;" :: "r"(d), "l"(src));
}
#define CP_COMMIT() asm volatile("cp.async.commit_group;")
#define CP_WAIT(n)  asm volatile("cp.async.wait_group %0;" :: "n"(n))

// ============================================================================
// Prep: build fp16 fragment-major operand tensors once.
// ============================================================================
__global__ void prep_kernel(const float* __restrict__ rw,
                            const float* __restrict__ A,
                            const float* __restrict__ Bm)
{
    const int nthr = gridDim.x * blockDim.x;
    const int tid0 = blockIdx.x * blockDim.x + threadIdx.x;
    // W1: rows 0-127 A, 128-135 router hi, 136-143 router lo residual
    for (int i = tid0; i < 144 * 2048; i += nthr) {
        int n = i >> 11, k = (i & 2047) * 2;
        float v0, v1;
        if (n < 128) {
            v0 = A[n * 4096 + k]; v1 = A[n * 4096 + k + 1];
        } else if (n < 136) {
            v0 = rw[(n - 128) * 4096 + k]; v1 = rw[(n - 128) * 4096 + k + 1];
        } else {
            float f0 = rw[(n - 136) * 4096 + k];
            float f1 = rw[(n - 136) * 4096 + k + 1];
            v0 = f0 - __half2float(__float2half_rn(f0));
            v1 = f1 - __half2float(__float2half_rn(f1));
        }
        int lane = (n & 7) * 4 + ((k & 7) >> 1);
        int idx = ((k >> 5) * W1_N8 + (n >> 3)) * 128
                + lane * 4 + ((k >> 4) & 1) * 2 + ((k >> 3) & 1);
        g_w1f[idx] = pack_f16x2(v0, v1);
    }
    // Bt: element (o, c): Bm[e][o][r]*SCALING, c = e*16+r
    for (int i = tid0; i < 4096 * 64; i += nthr) {
        int o = i >> 6, c = (i & 63) * 2;
        int e = c >> 4, r = c & 15;
        const float* bp = Bm + ((size_t)e * 4096 + o) * 16 + r;
        int idx = ((o >> 3) * 8 + (c >> 4)) * 64
                + ((o & 7) * 4 + ((c & 7) >> 1)) * 2 + ((c >> 3) & 1);
        g_btf[idx] = pack_f16x2(bp[0] * SCALING, bp[1] * SCALING);
    }
}

// ============================================================================
// GEMM1: C[N,144] = X @ W1^T (fp16 mma, compensated logits), fused gating,
// hw emitted directly in GEMM2 A-fragment order.
// 512 threads: 16 warps = 4 wm (32-row slabs) x 4 wn (32-col groups).
// Logits rotate across wn groups by t&3; partials combined via SMEM.
// ============================================================================
#define AS_WORDS  (4 * 128 * 32)          // 16384 (4 stages raw x)
#define WS_STAGE  (W1_N8 * 128)           // 2304 words per k32 stage
#define WS_WORDS  (4 * WS_STAGE)          // 9216
#define GW_WORDS  1024                    // [128][8] gates
#define LB_WORDS  (3 * 8 * 32 * 4)        // 3 partial-logit planes
#define SM1_WORDS (AS_WORDS + WS_WORDS + GW_WORDS + LB_WORDS)

__global__ __launch_bounds__(512, 1)
void gemm1_kernel(const float* __restrict__ x, const float* __restrict__ rb)
{
    extern __shared__ uint32_t smu[];
    uint32_t* As   = smu;
    uint32_t* Ws   = smu + AS_WORDS;
    float*    gw   = (float*)(smu + AS_WORDS + WS_WORDS);
    float*    lbuf = (float*)(smu + AS_WORDS + WS_WORDS + GW_WORDS);

    const int tid  = threadIdx.x;
    const int lane = tid & 31;
    const int warp = tid >> 5;
    const int wm   = warp & 3;        // 32-row slab (2 m16)
    const int wn   = warp >> 2;       // 0..3: 32-col group (4 n8)
    const int g    = lane >> 2;
    const int tig  = lane & 3;
    const int m0   = blockIdx.x * 128;

    float acc[2][5][4];               // [mt][4 A-tiles + logits][4]
#pragma unroll
    for (int mt = 0; mt < 2; mt++)
#pragma unroll
        for (int nt = 0; nt < 5; nt++)
#pragma unroll
            for (int i = 0; i < 4; i++) acc[mt][nt][i] = 0.f;

    auto issue = [&](int stage, int t) {
        const int k0 = t * 32;
        uint32_t* ab = As + stage * 128 * 32;
        uint32_t* wb = Ws + stage * WS_STAGE;
#pragma unroll
        for (int i = 0; i < 2; i++) {
            int idx = tid + i * 512, row = idx >> 3, c4 = idx & 7;
            int col = (4 * c4) ^ ((row & 7) * 4);
            cp16(ab + row * 32 + col, x + (size_t)(m0 + row) * DIM + k0 + 4 * c4);
        }
        // W frag slab: 2304 words = 576 uint4
#pragma unroll
        for (int i = 0; i < 2; i++) {
            int idx = tid + i * 512;
            if (idx < 576)
                cp16(wb + idx * 4, g_w1f + (size_t)t * WS_STAGE + idx * 4);
        }
    };

    issue(0, 0); CP_COMMIT();
    issue(1, 1); CP_COMMIT();
    issue(2, 2); CP_COMMIT();

    const int T = DIM / 32;   // 128
    for (int t = 0; t < T; ++t) {
        CP_WAIT(2);
        __syncthreads();
        if (t + 3 < T) issue((t + 3) & 3, t + 3);
        CP_COMMIT();

        const uint32_t* a = As + (t & 3) * 128 * 32;
        const uint32_t* w = Ws + (t & 3) * WS_STAGE;
        const bool do_logits = (wn == (t & 3));

        // B fragments for both k16 steps: one LDS.128 per n8
        uint4 bb[4];
#pragma unroll
        for (int nt = 0; nt < 4; ++nt)
            bb[nt] = *(const uint4*)(w + (wn * 4 + nt) * 128 + lane * 4);
        uint4 bh4, bl4;
        if (do_logits) {
            bh4 = *(const uint4*)(w + 16 * 128 + lane * 4);
            bl4 = *(const uint4*)(w + 17 * 128 + lane * 4);
        }

#pragma unroll
        for (int ks = 0; ks < 2; ++ks) {
            const int k = ks * 16;
            uint32_t af[2][4];
            float2 raw[2][4];
#pragma unroll
            for (int mt = 0; mt < 2; ++mt) {
                const int r0 = wm * 32 + mt * 16 + g;
                const int clo = k + 2 * tig, chi = k + 8 + 2 * tig;
                const int alo0 = r0 * 32 + (((clo & ~3) ^ ((r0 & 7) * 4)) | (clo & 3));
                const int alo1 = (r0 + 8) * 32 + (((clo & ~3) ^ (((r0 + 8) & 7) * 4)) | (clo & 3));
                const int ahi0 = r0 * 32 + (((chi & ~3) ^ ((r0 & 7) * 4)) | (chi & 3));
                const int ahi1 = (r0 + 8) * 32 + (((chi & ~3) ^ (((r0 + 8) & 7) * 4)) | (chi & 3));
                raw[mt][0] = *(const float2*)(a + alo0);
                raw[mt][1] = *(const float2*)(a + alo1);
                raw[mt][2] = *(const float2*)(a + ahi0);
                raw[mt][3] = *(const float2*)(a + ahi1);
#pragma unroll
                for (int j = 0; j < 4; j++)
                    af[mt][j] = pack_f16x2(raw[mt][j].x, raw[mt][j].y);
            }
#pragma unroll
            for (int nt = 0; nt < 4; ++nt) {
                uint32_t b0 = ks ? bb[nt].z : bb[nt].x;
                uint32_t b1 = ks ? bb[nt].w : bb[nt].y;
                mma_f16(acc[0][nt], af[0], b0, b1);
                mma_f16(acc[1][nt], af[1], b0, b1);
            }
            if (do_logits) {
                uint32_t alo[2][4];
#pragma unroll
                for (int mt = 0; mt < 2; ++mt)
#pragma unroll
                    for (int j = 0; j < 4; j++) {
                        float2 hv = unpack_f16x2(af[mt][j]);
                        alo[mt][j] = pack_f16x2(raw[mt][j].x - hv.x,
                                                raw[mt][j].y - hv.y);
                    }
                uint32_t h0 = ks ? bh4.z : bh4.x, h1 = ks ? bh4.w : bh4.y;
                uint32_t l0 = ks ? bl4.z : bl4.x, l1 = ks ? bl4.w : bl4.y;
                mma_f16(acc[0][4], af[0], h0, h1);
                mma_f16(acc[1][4], af[1], h0, h1);
                mma_f16(acc[0][4], af[0], l0, l1);
                mma_f16(acc[1][4], af[1], l0, l1);
                mma_f16(acc[0][4], alo[0], h0, h1);
                mma_f16(acc[1][4], alo[1], h0, h1);
            }
        }
    }

    // ---- combine partial logits: wn 0..2 -> SMEM, wn3 sums ----
    if (wn < 3) {
#pragma unroll
        for (int mt = 0; mt < 2; ++mt)
#pragma unroll
            for (int j = 0; j < 4; ++j)
                lbuf[(wn * 8 + wm * 2 + mt) * 128 + lane * 4 + j] = acc[mt][4][j];
    }
    __syncthreads();

    // ---- epilogue: router softmax -> top2 -> renorm gates (wn==3) ----
    if (wn == 3) {
        const float rb0 = rb[2 * tig];
        const float rb1 = rb[2 * tig + 1];
#pragma unroll
        for (int mt = 0; mt < 2; ++mt) {
#pragma unroll
            for (int p = 0; p < 3; ++p)
#pragma unroll
                for (int j = 0; j < 4; ++j)
                    acc[mt][4][j] += lbuf[(p * 8 + wm * 2 + mt) * 128 + lane * 4 + j];
#pragma unroll
            for (int half = 0; half < 2; ++half) {
                float l0 = acc[mt][4][half * 2 + 0] + rb0;
                float l1 = acc[mt][4][half * 2 + 1] + rb1;
                float m1, m2; int i1, i2;
                if (l0 >= l1) { m1 = l0; i1 = 2 * tig;     m2 = l1; i2 = 2 * tig + 1; }
                else          { m1 = l1; i1 = 2 * tig + 1; m2 = l0; i2 = 2 * tig; }
#pragma unroll
                for (int d = 1; d <= 2; d <<= 1) {
                    float om1 = __shfl_xor_sync(0xffffffffu, m1, d);
                    int   oi1 = __shfl_xor_sync(0xffffffffu, i1, d);
                    float om2 = __shfl_xor_sync(0xffffffffu, m2, d);
                    int   oi2 = __shfl_xor_sync(0xffffffffu, i2, d);
                    if (om1 > m1) {
                        if (m1 >= om2) { m2 = m1; i2 = i1; }
                        else           { m2 = om2; i2 = oi2; }
                        m1 = om1; i1 = oi1;
                    } else if (om1 > m2) { m2 = om1; i2 = oi1; }
                }
                float g1 = 1.f / (1.f + __expf(m2 - m1));
                float g2 = 1.f - g1;
                int row = wm * 32 + mt * 16 + half * 8 + g;
                gw[row * 8 + 2 * tig]     = (2 * tig     == i1) ? g1 : ((2 * tig     == i2) ? g2 : 0.f);
                gw[row * 8 + 2 * tig + 1] = (2 * tig + 1 == i1) ? g1 : ((2 * tig + 1 == i2) ? g2 : 0.f);
            }
        }
    }
    __syncthreads();

    // ---- gate h, pack fp16, store in GEMM2 A-fragment order ----
#pragma unroll
    for (int mt = 0; mt < 2; ++mt) {
#pragma unroll
        for (int nt = 0; nt < 4; ++nt) {
            const int col = wn * 32 + nt * 8 + 2 * tig;
            const int e  = col >> 4;
            const int ra = wm * 32 + mt * 16 + g;
            const float wa = gw[ra * 8 + e];
            const float wb = gw[(ra + 8) * 8 + e];
            uint32_t w0 = pack_f16x2(acc[mt][nt][0] * wa, acc[mt][nt][1] * wa);
            uint32_t w1 = pack_f16x2(acc[mt][nt][2] * wb, acc[mt][nt][3] * wb);
            const int m16 = (m0 + wm * 32 + mt * 16) >> 4;
            const int k16 = wn * 2 + (nt >> 1);
            *(uint2*)(g_hwf + ((size_t)m16 * 8 + k16) * 128
                            + lane * 4 + 2 * (nt & 1)) = make_uint2(w0, w1);
        }
    }
}

// ============================================================================
// GEMM2: out[N,4096] = hw @ Bt^T (fp16 mma).  (unchanged from R8)
// Block 128m x 128n, 8 warps of 32x64. B resident + A double-buffered,
// 96KB smem -> 2 CTAs/SM, grid 256 all-resident.
// ============================================================================
#define BS2_WORDS (16 * 8 * 64)
#define AS2_WORDS 8192
#define SM2_WORDS (BS2_WORDS + 2 * AS2_WORDS)

__global__ __launch_bounds__(256, 2)
void gemm2_kernel(float* __restrict__ out)
{
    extern __shared__ uint32_t smu[];
    uint32_t* Bs = smu;
    uint32_t* As = smu + BS2_WORDS;

    const int tid  = threadIdx.x;
    const int lane = tid & 31;
    const int warp = tid >> 5;
    const int wm   = warp & 3;
    const int wn   = warp >> 2;
    const int nb   = blockIdx.x & 31;
    const int mc   = blockIdx.x >> 5;

#pragma unroll
    for (int i = 0; i < 8; i++) {
        int idx = tid + i * 256;
        cp16(Bs + idx * 4, g_btf + (size_t)nb * 8192 + idx * 4);
    }
    CP_COMMIT();

    auto issueA = [&](int stage, int it) {
        const size_t src = (size_t)(mc * 16 + it) * 8192;
        uint32_t* dst = As + stage * AS2_WORDS;
#pragma unroll
        for (int i = 0; i < 8; i++) {
            int idx = tid + i * 256;
            cp16(dst + idx * 4, g_hwf + src + idx * 4);
        }
    };
    issueA(0, 0); CP_COMMIT();
    issueA(1, 1); CP_COMMIT();
    CP_WAIT(1);
    __syncthreads();

    const int n0 = nb * 128;
    for (int it = 0; it < 16; ++it) {
        const uint32_t* a = As + (it & 1) * AS2_WORDS;

        float acc[2][8][4];
#pragma unroll
        for (int mt = 0; mt < 2; mt++)
#pragma unroll
            for (int nt = 0; nt < 8; nt++)
#pragma unroll
                for (int i = 0; i < 4; i++) acc[mt][nt][i] = 0.f;

#pragma unroll
        for (int ks = 0; ks < 8; ++ks) {
            uint4 af[2];
#pragma unroll
            for (int mt = 0; mt < 2; mt++)
                af[mt] = *(const uint4*)(a + ((wm * 2 + mt) * 8 + ks) * 128 + lane * 4);
            uint2 bf[8];
#pragma unroll
            for (int nt = 0; nt < 8; nt++) {
                const int n8l = wn * 8 + nt;
                bf[nt] = *(const uint2*)(Bs + (n8l * 8 + ks) * 64 + lane * 2);
            }
#pragma unroll
            for (int nt = 0; nt < 8; nt++)
#pragma unroll
                for (int mt = 0; mt < 2; mt++)
                    mma_f16(acc[mt][nt], (const uint32_t*)&af[mt], bf[nt].x, bf[nt].y);
        }

        {
            const int g   = lane >> 2;
            const int tig = lane & 3;
            const int mbase = (mc * 16 + it) * 128;
#pragma unroll
            for (int mt = 0; mt < 2; ++mt) {
#pragma unroll
                for (int nt = 0; nt < 8; ++nt) {
                    const int col = n0 + wn * 64 + nt * 8 + 2 * tig;
                    const int ra  = mbase + wm * 32 + mt * 16 + g;
                    *(float2*)(out + (size_t)ra * OUT_D + col) =
                        make_float2(acc[mt][nt][0], acc[mt][nt][1]);
                    *(float2*)(out + (size_t)(ra + 8) * OUT_D + col) =
                        make_float2(acc[mt][nt][2], acc[mt][nt][3]);
                }
            }
        }

        __syncthreads();
        if (it + 2 < 16) issueA(it & 1, it + 2);
        CP_COMMIT();
        CP_WAIT(1);
        __syncthreads();
    }
}

// ============================================================================
extern "C" void kernel_launch(void* const* d_in, const int* in_sizes, int n_in,
                              void* d_out, int out_size)
{
    const float* x  = (const float*)d_in[0];   // [N, 4096]
    const float* rw = (const float*)d_in[1];   // [8, 4096]
    const float* rb = (const float*)d_in[2];   // [8]
    const float* A  = (const float*)d_in[3];   // [8,16,4096]
    const float* Bm = (const float*)d_in[4];   // [8,4096,16]
    float* out = (float*)d_out;                // [N, 4096] fp32

    const int sm1 = SM1_WORDS * 4;   // ~120 KB
    const int sm2 = SM2_WORDS * 4;   // 98304 B
    cudaFuncSetAttribute(gemm1_kernel,
                         cudaFuncAttributeMaxDynamicSharedMemorySize, sm1);
    cudaFuncSetAttribute(gemm2_kernel,
                         cudaFuncAttributeMaxDynamicSharedMemorySize, sm2);

    prep_kernel<<<1024, 256>>>(rw, A, Bm);
    gemm1_kernel<<<N_TOK / 128, 512, sm1>>>(x, rb);
    gemm2_kernel<<<256, 256, sm2>>>(out);
}

// round 10
// speedup vs baseline: 1.2118x; 1.2118x over previous
#include <cuda_runtime.h>
#include <cuda_fp16.h>
#include <cstdint>
#include <cstddef>

// Problem constants: B=4, S=4096 -> N=16384 tokens
#define N_TOK 16384
#define DIM   4096
#define OUT_D 4096
#define SCALING 0.5f
#define W1_N8 18   // 144 rows / 8: 16 A-blocks + router-hi + router-lo

// -------- static scratch, fp16 fragment-major (m16n8k16) --------
// GEMM1 B operand: [k16 0..255][n8 0..17][lane*2 + reg]  (reg=(k>>3)&1)
__device__ __align__(16) uint32_t g_w1f[256 * W1_N8 * 64];
// GEMM2 B operand: [n8 0..511][k16 0..7][lane*2 + reg]
__device__ __align__(16) uint32_t g_btf[512 * 8 * 64];
// GEMM2 A operand: [m16 0..1023][k16 0..7][lane*4 + reg]
__device__ __align__(16) uint32_t g_hwf[(size_t)1024 * 8 * 128];

// -------- helpers --------
__device__ __forceinline__ uint32_t pack_f16x2(float lo, float hi) {
    uint32_t r;   // d.low = 2nd src, d.high = 1st src
    asm("cvt.rn.f16x2.f32 %0, %1, %2;" : "=r"(r) : "f"(hi), "f"(lo));
    return r;
}
__device__ __forceinline__ float2 unpack_f16x2(uint32_t v) {
    __half2 h = *(__half2*)&v;
    return __half22float2(h);
}
__device__ __forceinline__ void mma_f16(float* c, const uint32_t* a,
                                        uint32_t b0, uint32_t b1) {
    asm volatile(
        "mma.sync.aligned.m16n8k16.row.col.f32.f16.f16.f32 "
        "{%0,%1,%2,%3}, {%4,%5,%6,%7}, {%8,%9}, {%0,%1,%2,%3};\n"
        : "+f"(c[0]), "+f"(c[1]), "+f"(c[2]), "+f"(c[3])
        : "r"(a[0]), "r"(a[1]), "r"(a[2]), "r"(a[3]), "r"(b0), "r"(b1));
}
__device__ __forceinline__ void cp16(void* dst, const void* src) {
    uint32_t d = (uint32_t)__cvta_generic_to_shared(dst);
    asm volatile("cp.async.cg.shared.global [%0], [%1], 16;" :: "r"(d), "l"(src));
}
#define CP_COMMIT() asm volatile("cp.async.commit_group;")
#define CP_WAIT(n)  asm volatile("cp.async.wait_group %0;" :: "n"(n))

// ============================================================================
// Prep: build fp16 fragment-major operand tensors once.
// B-frag map (col-major n8 x k16): lane=(n&7)*4+((k&7)>>1), reg=(k>>3)&1, half=k&1
// A-frag map (row-major m16 x k16): lane=(r&7)*4+((c&7)>>1), reg=(r>>3)+2*(c>>3)
// ============================================================================
__global__ void prep_kernel(const float* __restrict__ rw,
                            const float* __restrict__ A,
                            const float* __restrict__ Bm)
{
    const int nthr = gridDim.x * blockDim.x;
    const int tid0 = blockIdx.x * blockDim.x + threadIdx.x;
    // W1: rows 0-127 A, 128-135 router hi, 136-143 router lo residual
    for (int i = tid0; i < 144 * 2048; i += nthr) {
        int n = i >> 11, k = (i & 2047) * 2;
        float v0, v1;
        if (n < 128) {
            v0 = A[n * 4096 + k]; v1 = A[n * 4096 + k + 1];
        } else if (n < 136) {
            v0 = rw[(n - 128) * 4096 + k]; v1 = rw[(n - 128) * 4096 + k + 1];
        } else {
            float f0 = rw[(n - 136) * 4096 + k];
            float f1 = rw[(n - 136) * 4096 + k + 1];
            v0 = f0 - __half2float(__float2half_rn(f0));
            v1 = f1 - __half2float(__float2half_rn(f1));
        }
        int idx = ((k >> 4) * W1_N8 + (n >> 3)) * 64
                + ((n & 7) * 4 + ((k & 7) >> 1)) * 2 + ((k >> 3) & 1);
        g_w1f[idx] = pack_f16x2(v0, v1);
    }
    // Bt: element (o, c): Bm[e][o][r]*SCALING, c = e*16+r
    for (int i = tid0; i < 4096 * 64; i += nthr) {
        int o = i >> 6, c = (i & 63) * 2;
        int e = c >> 4, r = c & 15;
        const float* bp = Bm + ((size_t)e * 4096 + o) * 16 + r;
        int idx = ((o >> 3) * 8 + (c >> 4)) * 64
                + ((o & 7) * 4 + ((c & 7) >> 1)) * 2 + ((c >> 3) & 1);
        g_btf[idx] = pack_f16x2(bp[0] * SCALING, bp[1] * SCALING);
    }
}

// ============================================================================
// GEMM1: C[N,144] = X @ W1^T (fp16 mma, compensated logits), fused gating,
// hw emitted directly in GEMM2 A-fragment order.
// R7 warp shape (8 warps: 4 wm x 2 wn), but 4 stages of k64 (2 k32 tiles
// per stage): half the barriers, 2x independent work between barriers.
// ============================================================================
#define AT_WORDS  (128 * 32)              // one k32 x-tile: 4096 words
#define AS_STAGE  (2 * AT_WORDS)          // k64 stage: 8192 words
#define AS_WORDS  (4 * AS_STAGE)          // 32768 (128 KB)
#define WT_WORDS  (2 * W1_N8 * 64)        // one k32 W slab: 2304 words
#define WS_STAGE  (2 * WT_WORDS)          // 4608
#define WS_WORDS  (4 * WS_STAGE)          // 18432 (72 KB)
#define SM1_WORDS (AS_WORDS + WS_WORDS + 1024 + 1024)

__global__ __launch_bounds__(256, 1)
void gemm1_kernel(const float* __restrict__ x, const float* __restrict__ rb)
{
    extern __shared__ uint32_t smu[];
    uint32_t* As   = smu;
    uint32_t* Ws   = smu + AS_WORDS;
    float*    gw   = (float*)(smu + AS_WORDS + WS_WORDS);          // [128][8]
    float*    lbuf = (float*)(smu + AS_WORDS + WS_WORDS + 1024);   // [8][32][4]

    const int tid  = threadIdx.x;
    const int lane = tid & 31;
    const int warp = tid >> 5;
    const int wm   = warp & 3;
    const int wn   = warp >> 2;
    const int g    = lane >> 2;
    const int tig  = lane & 3;
    const int m0   = blockIdx.x * 128;
    const int ncol0 = wn * 64;

    float acc[2][9][4];
#pragma unroll
    for (int mt = 0; mt < 2; mt++)
#pragma unroll
        for (int nt = 0; nt < 9; nt++)
#pragma unroll
            for (int i = 0; i < 4; i++) acc[mt][nt][i] = 0.f;

    // issue one k64 stage = two consecutive k32 tiles (2u, 2u+1)
    auto issue = [&](int stage, int u) {
        uint32_t* ab = As + stage * AS_STAGE;
        uint32_t* wb = Ws + stage * WS_STAGE;
#pragma unroll
        for (int sub = 0; sub < 2; ++sub) {
            const int t  = 2 * u + sub;
            const int k0 = t * 32;
            uint32_t* a = ab + sub * AT_WORDS;
            uint32_t* w = wb + sub * WT_WORDS;
#pragma unroll
            for (int i = 0; i < 4; i++) {
                int idx = tid + i * 256, row = idx >> 3, c4 = idx & 7;
                int col = (4 * c4) ^ ((row & 7) * 4);
                cp16(a + row * 32 + col, x + (size_t)(m0 + row) * DIM + k0 + 4 * c4);
            }
#pragma unroll
            for (int i = 0; i < 3; i++) {
                int idx = tid + i * 256;
                if (idx < 576)
                    cp16(w + idx * 4, g_w1f + (size_t)t * WT_WORDS + idx * 4);
            }
        }
    };

    issue(0, 0); CP_COMMIT();
    issue(1, 1); CP_COMMIT();
    issue(2, 2); CP_COMMIT();

    const int U = DIM / 64;   // 64 k64 stages
    for (int u = 0; u < U; ++u) {
        CP_WAIT(2);
        __syncthreads();
        if (u + 3 < U) issue((u + 3) & 3, u + 3);
        CP_COMMIT();

#pragma unroll
        for (int sub = 0; sub < 2; ++sub) {
            const int t = 2 * u + sub;
            const uint32_t* a = As + (u & 3) * AS_STAGE + sub * AT_WORDS;
            const uint32_t* w = Ws + (u & 3) * WS_STAGE + sub * WT_WORDS;
            const bool do_logits = (wn == (t & 1));
#pragma unroll
            for (int ks = 0; ks < 2; ++ks) {
                const int k = ks * 16;
                uint32_t af[2][4];
                float2 raw[2][4];
#pragma unroll
                for (int mt = 0; mt < 2; ++mt) {
                    const int r0 = wm * 32 + mt * 16 + g;
                    const int clo = k + 2 * tig, chi = k + 8 + 2 * tig;
                    const int alo0 = r0 * 32 + (((clo & ~3) ^ ((r0 & 7) * 4)) | (clo & 3));
                    const int alo1 = (r0 + 8) * 32 + (((clo & ~3) ^ (((r0 + 8) & 7) * 4)) | (clo & 3));
                    const int ahi0 = r0 * 32 + (((chi & ~3) ^ ((r0 & 7) * 4)) | (chi & 3));
                    const int ahi1 = (r0 + 8) * 32 + (((chi & ~3) ^ (((r0 + 8) & 7) * 4)) | (chi & 3));
                    raw[mt][0] = *(const float2*)(a + alo0);
                    raw[mt][1] = *(const float2*)(a + alo1);
                    raw[mt][2] = *(const float2*)(a + ahi0);
                    raw[mt][3] = *(const float2*)(a + ahi1);
#pragma unroll
                    for (int j = 0; j < 4; j++)
                        af[mt][j] = pack_f16x2(raw[mt][j].x, raw[mt][j].y);
                }
#pragma unroll
                for (int nt = 0; nt < 8; ++nt) {
                    const int n8 = wn * 8 + nt;
                    uint2 bb = *(const uint2*)(w + (ks * W1_N8 + n8) * 64 + lane * 2);
                    mma_f16(acc[0][nt], af[0], bb.x, bb.y);
                    mma_f16(acc[1][nt], af[1], bb.x, bb.y);
                }
                if (do_logits) {
                    uint32_t alo[2][4];
#pragma unroll
                    for (int mt = 0; mt < 2; ++mt)
#pragma unroll
                        for (int j = 0; j < 4; j++) {
                            float2 hv = unpack_f16x2(af[mt][j]);
                            alo[mt][j] = pack_f16x2(raw[mt][j].x - hv.x,
                                                    raw[mt][j].y - hv.y);
                        }
                    uint2 bh = *(const uint2*)(w + (ks * W1_N8 + 16) * 64 + lane * 2);
                    uint2 bl = *(const uint2*)(w + (ks * W1_N8 + 17) * 64 + lane * 2);
                    mma_f16(acc[0][8], af[0], bh.x, bh.y);
                    mma_f16(acc[1][8], af[1], bh.x, bh.y);
                    mma_f16(acc[0][8], af[0], bl.x, bl.y);
                    mma_f16(acc[1][8], af[1], bl.x, bl.y);
                    mma_f16(acc[0][8], alo[0], bh.x, bh.y);
                    mma_f16(acc[1][8], alo[1], bh.x, bh.y);
                }
            }
        }
    }

    // ---- combine partial logits: wn0 -> SMEM, wn1 adds ----
    if (wn == 0) {
#pragma unroll
        for (int mt = 0; mt < 2; ++mt)
#pragma unroll
            for (int j = 0; j < 4; ++j)
                lbuf[((wm * 2 + mt) * 32 + lane) * 4 + j] = acc[mt][8][j];
    }
    __syncthreads();

    // ---- epilogue: router softmax -> top2 -> renorm gates (wn==1) ----
    if (wn == 1) {
        const float rb0 = rb[2 * tig];
        const float rb1 = rb[2 * tig + 1];
#pragma unroll
        for (int mt = 0; mt < 2; ++mt) {
#pragma unroll
            for (int j = 0; j < 4; ++j)
                acc[mt][8][j] += lbuf[((wm * 2 + mt) * 32 + lane) * 4 + j];
#pragma unroll
            for (int half = 0; half < 2; ++half) {
                float l0 = acc[mt][8][half * 2 + 0] + rb0;
                float l1 = acc[mt][8][half * 2 + 1] + rb1;
                float m1, m2; int i1, i2;
                if (l0 >= l1) { m1 = l0; i1 = 2 * tig;     m2 = l1; i2 = 2 * tig + 1; }
                else          { m1 = l1; i1 = 2 * tig + 1; m2 = l0; i2 = 2 * tig; }
#pragma unroll
                for (int d = 1; d <= 2; d <<= 1) {
                    float om1 = __shfl_xor_sync(0xffffffffu, m1, d);
                    int   oi1 = __shfl_xor_sync(0xffffffffu, i1, d);
                    float om2 = __shfl_xor_sync(0xffffffffu, m2, d);
                    int   oi2 = __shfl_xor_sync(0xffffffffu, i2, d);
                    if (om1 > m1) {
                        if (m1 >= om2) { m2 = m1; i2 = i1; }
                        else           { m2 = om2; i2 = oi2; }
                        m1 = om1; i1 = oi1;
                    } else if (om1 > m2) { m2 = om1; i2 = oi1; }
                }
                float g1 = 1.f / (1.f + __expf(m2 - m1));
                float g2 = 1.f - g1;
                int row = wm * 32 + mt * 16 + half * 8 + g;
                gw[row * 8 + 2 * tig]     = (2 * tig     == i1) ? g1 : ((2 * tig     == i2) ? g2 : 0.f);
                gw[row * 8 + 2 * tig + 1] = (2 * tig + 1 == i1) ? g1 : ((2 * tig + 1 == i2) ? g2 : 0.f);
            }
        }
    }
    __syncthreads();

    // ---- gate h, pack fp16, store in GEMM2 A-fragment order ----
#pragma unroll
    for (int mt = 0; mt < 2; ++mt) {
#pragma unroll
        for (int nt = 0; nt < 8; ++nt) {
            const int col = ncol0 + nt * 8 + 2 * tig;
            const int e  = col >> 4;
            const int ra = wm * 32 + mt * 16 + g;
            const float wa = gw[ra * 8 + e];
            const float wb = gw[(ra + 8) * 8 + e];
            uint32_t w0 = pack_f16x2(acc[mt][nt][0] * wa, acc[mt][nt][1] * wa);
            uint32_t w1 = pack_f16x2(acc[mt][nt][2] * wb, acc[mt][nt][3] * wb);
            const int m16 = (m0 + wm * 32 + mt * 16) >> 4;
            const int k16 = wn * 4 + (nt >> 1);
            *(uint2*)(g_hwf + ((size_t)m16 * 8 + k16) * 128
                            + lane * 4 + 2 * (nt & 1)) = make_uint2(w0, w1);
        }
    }
}

// ============================================================================
// GEMM2: out[N,4096] = hw @ Bt^T (fp16 mma).  (unchanged from R8)
// Block 128m x 128n, 8 warps of 32x64. B resident + A double-buffered,
// 96KB smem -> 2 CTAs/SM, grid 256 all-resident.
// ============================================================================
#define BS2_WORDS (16 * 8 * 64)
#define AS2_WORDS 8192
#define SM2_WORDS (BS2_WORDS + 2 * AS2_WORDS)

__global__ __launch_bounds__(256, 2)
void gemm2_kernel(float* __restrict__ out)
{
    extern __shared__ uint32_t smu[];
    uint32_t* Bs = smu;
    uint32_t* As = smu + BS2_WORDS;

    const int tid  = threadIdx.x;
    const int lane = tid & 31;
    const int warp = tid >> 5;
    const int wm   = warp & 3;
    const int wn   = warp >> 2;
    const int nb   = blockIdx.x & 31;
    const int mc   = blockIdx.x >> 5;

#pragma unroll
    for (int i = 0; i < 8; i++) {
        int idx = tid + i * 256;
        cp16(Bs + idx * 4, g_btf + (size_t)nb * 8192 + idx * 4);
    }
    CP_COMMIT();

    auto issueA = [&](int stage, int it) {
        const size_t src = (size_t)(mc * 16 + it) * 8192;
        uint32_t* dst = As + stage * AS2_WORDS;
#pragma unroll
        for (int i = 0; i < 8; i++) {
            int idx = tid + i * 256;
            cp16(dst + idx * 4, g_hwf + src + idx * 4);
        }
    };
    issueA(0, 0); CP_COMMIT();
    issueA(1, 1); CP_COMMIT();
    CP_WAIT(1);
    __syncthreads();

    const int n0 = nb * 128;
    for (int it = 0; it < 16; ++it) {
        const uint32_t* a = As + (it & 1) * AS2_WORDS;

        float acc[2][8][4];
#pragma unroll
        for (int mt = 0; mt < 2; mt++)
#pragma unroll
            for (int nt = 0; nt < 8; nt++)
#pragma unroll
                for (int i = 0; i < 4; i++) acc[mt][nt][i] = 0.f;

#pragma unroll
        for (int ks = 0; ks < 8; ++ks) {
            uint4 af[2];
#pragma unroll
            for (int mt = 0; mt < 2; mt++)
                af[mt] = *(const uint4*)(a + ((wm * 2 + mt) * 8 + ks) * 128 + lane * 4);
            uint2 bf[8];
#pragma unroll
            for (int nt = 0; nt < 8; nt++) {
                const int n8l = wn * 8 + nt;
                bf[nt] = *(const uint2*)(Bs + (n8l * 8 + ks) * 64 + lane * 2);
            }
#pragma unroll
            for (int nt = 0; nt < 8; nt++)
#pragma unroll
                for (int mt = 0; mt < 2; mt++)
                    mma_f16(acc[mt][nt], (const uint32_t*)&af[mt], bf[nt].x, bf[nt].y);
        }

        {
            const int g   = lane >> 2;
            const int tig = lane & 3;
            const int mbase = (mc * 16 + it) * 128;
#pragma unroll
            for (int mt = 0; mt < 2; ++mt) {
#pragma unroll
                for (int nt = 0; nt < 8; ++nt) {
                    const int col = n0 + wn * 64 + nt * 8 + 2 * tig;
                    const int ra  = mbase + wm * 32 + mt * 16 + g;
                    *(float2*)(out + (size_t)ra * OUT_D + col) =
                        make_float2(acc[mt][nt][0], acc[mt][nt][1]);
                    *(float2*)(out + (size_t)(ra + 8) * OUT_D + col) =
                        make_float2(acc[mt][nt][2], acc[mt][nt][3]);
                }
            }
        }

        __syncthreads();
        if (it + 2 < 16) issueA(it & 1, it + 2);
        CP_COMMIT();
        CP_WAIT(1);
        __syncthreads();
    }
}

// ============================================================================
extern "C" void kernel_launch(void* const* d_in, const int* in_sizes, int n_in,
                              void* d_out, int out_size)
{
    const float* x  = (const float*)d_in[0];   // [N, 4096]
    const float* rw = (const float*)d_in[1];   // [8, 4096]
    const float* rb = (const float*)d_in[2];   // [8]
    const float* A  = (const float*)d_in[3];   // [8,16,4096]
    const float* Bm = (const float*)d_in[4];   // [8,4096,16]
    float* out = (float*)d_out;                // [N, 4096] fp32

    const int sm1 = SM1_WORDS * 4;   // 212992 B
    const int sm2 = SM2_WORDS * 4;   // 98304 B
    cudaFuncSetAttribute(gemm1_kernel,
                         cudaFuncAttributeMaxDynamicSharedMemorySize, sm1);
    cudaFuncSetAttribute(gemm2_kernel,
                         cudaFuncAttributeMaxDynamicSharedMemorySize, sm2);

    prep_kernel<<<1024, 256>>>(rw, A, Bm);
    gemm1_kernel<<<N_TOK / 128, 256, sm1>>>(x, rb);
    gemm2_kernel<<<256, 256, sm2>>>(out);
}

// round 12
// speedup vs baseline: 1.2500x; 1.0315x over previous
#include <cuda_runtime.h>
#include <cuda_fp16.h>
#include <cstdint>
#include <cstddef>

// Problem constants: B=4, S=4096 -> N=16384 tokens
#define N_TOK 16384
#define DIM   4096
#define OUT_D 4096
#define SCALING 0.5f
#define W1_N8 18   // 144 rows / 8: 16 A-blocks + router-hi + router-lo

// -------- static scratch, fp16 fragment-major (m16n8k16) --------
// GEMM1 B operand: [k16 0..255][n8 0..17][lane*2 + reg]  (reg=(k>>3)&1)
__device__ __align__(16) uint32_t g_w1f[256 * W1_N8 * 64];
// GEMM2 B operand: [n8 0..511][k16 0..7][lane*2 + reg]
__device__ __align__(16) uint32_t g_btf[512 * 8 * 64];
// GEMM2 A operand: [m16 0..1023][k16 0..7][lane*4 + reg]
__device__ __align__(16) uint32_t g_hwf[(size_t)1024 * 8 * 128];

// -------- helpers --------
__device__ __forceinline__ uint32_t pack_f16x2(float lo, float hi) {
    uint32_t r;   // d.low = 2nd src, d.high = 1st src
    asm("cvt.rn.f16x2.f32 %0, %1, %2;" : "=r"(r) : "f"(hi), "f"(lo));
    return r;
}
__device__ __forceinline__ float2 unpack_f16x2(uint32_t v) {
    __half2 h = *(__half2*)&v;
    return __half22float2(h);
}
__device__ __forceinline__ void mma_f16(float* c, const uint32_t* a,
                                        uint32_t b0, uint32_t b1) {
    asm volatile(
        "mma.sync.aligned.m16n8k16.row.col.f32.f16.f16.f32 "
        "{%0,%1,%2,%3}, {%4,%5,%6,%7}, {%8,%9}, {%0,%1,%2,%3};\n"
        : "+f"(c[0]), "+f"(c[1]), "+f"(c[2]), "+f"(c[3])
        : "r"(a[0]), "r"(a[1]), "r"(a[2]), "r"(a[3]), "r"(b0), "r"(b1));
}
__device__ __forceinline__ void cp16(void* dst, const void* src) {
    uint32_t d = (uint32_t)__cvta_generic_to_shared(dst);
    asm volatile("cp.async.cg.shared.global [%0], [%1], 16;" :: "r"(d), "l"(src));
}
#define CP_COMMIT() asm volatile("cp.async.commit_group;")
#define CP_WAIT(n)  asm volatile("cp.async.wait_group %0;" :: "n"(n))

// ============================================================================
// Prep: build fp16 fragment-major operand tensors once. (unchanged from R10)
// ============================================================================
__global__ void prep_kernel(const float* __restrict__ rw,
                            const float* __restrict__ A,
                            const float* __restrict__ Bm)
{
    const int nthr = gridDim.x * blockDim.x;
    const int tid0 = blockIdx.x * blockDim.x + threadIdx.x;
    for (int i = tid0; i < 144 * 2048; i += nthr) {
        int n = i >> 11, k = (i & 2047) * 2;
        float v0, v1;
        if (n < 128) {
            v0 = A[n * 4096 + k]; v1 = A[n * 4096 + k + 1];
        } else if (n < 136) {
            v0 = rw[(n - 128) * 4096 + k]; v1 = rw[(n - 128) * 4096 + k + 1];
        } else {
            float f0 = rw[(n - 136) * 4096 + k];
            float f1 = rw[(n - 136) * 4096 + k + 1];
            v0 = f0 - __half2float(__float2half_rn(f0));
            v1 = f1 - __half2float(__float2half_rn(f1));
        }
        int idx = ((k >> 4) * W1_N8 + (n >> 3)) * 64
                + ((n & 7) * 4 + ((k & 7) >> 1)) * 2 + ((k >> 3) & 1);
        g_w1f[idx] = pack_f16x2(v0, v1);
    }
    for (int i = tid0; i < 4096 * 64; i += nthr) {
        int o = i >> 6, c = (i & 63) * 2;
        int e = c >> 4, r = c & 15;
        const float* bp = Bm + ((size_t)e * 4096 + o) * 16 + r;
        int idx = ((o >> 3) * 8 + (c >> 4)) * 64
                + ((o & 7) * 4 + ((c & 7) >> 1)) * 2 + ((c >> 3) & 1);
        g_btf[idx] = pack_f16x2(bp[0] * SCALING, bp[1] * SCALING);
    }
}

// ============================================================================
// GEMM1 (unchanged from R10 — k64 stages, ring 4, 64 barriers)
// ============================================================================
#define AT_WORDS  (128 * 32)
#define AS_STAGE  (2 * AT_WORDS)
#define AS_WORDS  (4 * AS_STAGE)
#define WT_WORDS  (2 * W1_N8 * 64)
#define WS_STAGE  (2 * WT_WORDS)
#define WS_WORDS  (4 * WS_STAGE)
#define SM1_WORDS (AS_WORDS + WS_WORDS + 1024 + 1024)

__global__ __launch_bounds__(256, 1)
void gemm1_kernel(const float* __restrict__ x, const float* __restrict__ rb)
{
    extern __shared__ uint32_t smu[];
    uint32_t* As   = smu;
    uint32_t* Ws   = smu + AS_WORDS;
    float*    gw   = (float*)(smu + AS_WORDS + WS_WORDS);
    float*    lbuf = (float*)(smu + AS_WORDS + WS_WORDS + 1024);

    const int tid  = threadIdx.x;
    const int lane = tid & 31;
    const int warp = tid >> 5;
    const int wm   = warp & 3;
    const int wn   = warp >> 2;
    const int g    = lane >> 2;
    const int tig  = lane & 3;
    const int m0   = blockIdx.x * 128;
    const int ncol0 = wn * 64;

    float acc[2][9][4];
#pragma unroll
    for (int mt = 0; mt < 2; mt++)
#pragma unroll
        for (int nt = 0; nt < 9; nt++)
#pragma unroll
            for (int i = 0; i < 4; i++) acc[mt][nt][i] = 0.f;

    auto issue = [&](int stage, int u) {
        uint32_t* ab = As + stage * AS_STAGE;
        uint32_t* wb = Ws + stage * WS_STAGE;
#pragma unroll
        for (int sub = 0; sub < 2; ++sub) {
            const int t  = 2 * u + sub;
            const int k0 = t * 32;
            uint32_t* a = ab + sub * AT_WORDS;
            uint32_t* w = wb + sub * WT_WORDS;
#pragma unroll
            for (int i = 0; i < 4; i++) {
                int idx = tid + i * 256, row = idx >> 3, c4 = idx & 7;
                int col = (4 * c4) ^ ((row & 7) * 4);
                cp16(a + row * 32 + col, x + (size_t)(m0 + row) * DIM + k0 + 4 * c4);
            }
#pragma unroll
            for (int i = 0; i < 3; i++) {
                int idx = tid + i * 256;
                if (idx < 576)
                    cp16(w + idx * 4, g_w1f + (size_t)t * WT_WORDS + idx * 4);
            }
        }
    };

    issue(0, 0); CP_COMMIT();
    issue(1, 1); CP_COMMIT();
    issue(2, 2); CP_COMMIT();

    const int U = DIM / 64;
    for (int u = 0; u < U; ++u) {
        CP_WAIT(2);
        __syncthreads();
        if (u + 3 < U) issue((u + 3) & 3, u + 3);
        CP_COMMIT();

#pragma unroll
        for (int sub = 0; sub < 2; ++sub) {
            const int t = 2 * u + sub;
            const uint32_t* a = As + (u & 3) * AS_STAGE + sub * AT_WORDS;
            const uint32_t* w = Ws + (u & 3) * WS_STAGE + sub * WT_WORDS;
            const bool do_logits = (wn == (t & 1));
#pragma unroll
            for (int ks = 0; ks < 2; ++ks) {
                const int k = ks * 16;
                uint32_t af[2][4];
                float2 raw[2][4];
#pragma unroll
                for (int mt = 0; mt < 2; ++mt) {
                    const int r0 = wm * 32 + mt * 16 + g;
                    const int clo = k + 2 * tig, chi = k + 8 + 2 * tig;
                    const int alo0 = r0 * 32 + (((clo & ~3) ^ ((r0 & 7) * 4)) | (clo & 3));
                    const int alo1 = (r0 + 8) * 32 + (((clo & ~3) ^ (((r0 + 8) & 7) * 4)) | (clo & 3));
                    const int ahi0 = r0 * 32 + (((chi & ~3) ^ ((r0 & 7) * 4)) | (chi & 3));
                    const int ahi1 = (r0 + 8) * 32 + (((chi & ~3) ^ (((r0 + 8) & 7) * 4)) | (chi & 3));
                    raw[mt][0] = *(const float2*)(a + alo0);
                    raw[mt][1] = *(const float2*)(a + alo1);
                    raw[mt][2] = *(const float2*)(a + ahi0);
                    raw[mt][3] = *(const float2*)(a + ahi1);
#pragma unroll
                    for (int j = 0; j < 4; j++)
                        af[mt][j] = pack_f16x2(raw[mt][j].x, raw[mt][j].y);
                }
#pragma unroll
                for (int nt = 0; nt < 8; ++nt) {
                    const int n8 = wn * 8 + nt;
                    uint2 bb = *(const uint2*)(w + (ks * W1_N8 + n8) * 64 + lane * 2);
                    mma_f16(acc[0][nt], af[0], bb.x, bb.y);
                    mma_f16(acc[1][nt], af[1], bb.x, bb.y);
                }
                if (do_logits) {
                    uint32_t alo[2][4];
#pragma unroll
                    for (int mt = 0; mt < 2; ++mt)
#pragma unroll
                        for (int j = 0; j < 4; j++) {
                            float2 hv = unpack_f16x2(af[mt][j]);
                            alo[mt][j] = pack_f16x2(raw[mt][j].x - hv.x,
                                                    raw[mt][j].y - hv.y);
                        }
                    uint2 bh = *(const uint2*)(w + (ks * W1_N8 + 16) * 64 + lane * 2);
                    uint2 bl = *(const uint2*)(w + (ks * W1_N8 + 17) * 64 + lane * 2);
                    mma_f16(acc[0][8], af[0], bh.x, bh.y);
                    mma_f16(acc[1][8], af[1], bh.x, bh.y);
                    mma_f16(acc[0][8], af[0], bl.x, bl.y);
                    mma_f16(acc[1][8], af[1], bl.x, bl.y);
                    mma_f16(acc[0][8], alo[0], bh.x, bh.y);
                    mma_f16(acc[1][8], alo[1], bh.x, bh.y);
                }
            }
        }
    }

    if (wn == 0) {
#pragma unroll
        for (int mt = 0; mt < 2; ++mt)
#pragma unroll
            for (int j = 0; j < 4; ++j)
                lbuf[((wm * 2 + mt) * 32 + lane) * 4 + j] = acc[mt][8][j];
    }
    __syncthreads();

    if (wn == 1) {
        const float rb0 = rb[2 * tig];
        const float rb1 = rb[2 * tig + 1];
#pragma unroll
        for (int mt = 0; mt < 2; ++mt) {
#pragma unroll
            for (int j = 0; j < 4; ++j)
                acc[mt][8][j] += lbuf[((wm * 2 + mt) * 32 + lane) * 4 + j];
#pragma unroll
            for (int half = 0; half < 2; ++half) {
                float l0 = acc[mt][8][half * 2 + 0] + rb0;
                float l1 = acc[mt][8][half * 2 + 1] + rb1;
                float m1, m2; int i1, i2;
                if (l0 >= l1) { m1 = l0; i1 = 2 * tig;     m2 = l1; i2 = 2 * tig + 1; }
                else          { m1 = l1; i1 = 2 * tig + 1; m2 = l0; i2 = 2 * tig; }
#pragma unroll
                for (int d = 1; d <= 2; d <<= 1) {
                    float om1 = __shfl_xor_sync(0xffffffffu, m1, d);
                    int   oi1 = __shfl_xor_sync(0xffffffffu, i1, d);
                    float om2 = __shfl_xor_sync(0xffffffffu, m2, d);
                    int   oi2 = __shfl_xor_sync(0xffffffffu, i2, d);
                    if (om1 > m1) {
                        if (m1 >= om2) { m2 = m1; i2 = i1; }
                        else           { m2 = om2; i2 = oi2; }
                        m1 = om1; i1 = oi1;
                    } else if (om1 > m2) { m2 = om1; i2 = oi1; }
                }
                float g1 = 1.f / (1.f + __expf(m2 - m1));
                float g2 = 1.f - g1;
                int row = wm * 32 + mt * 16 + half * 8 + g;
                gw[row * 8 + 2 * tig]     = (2 * tig     == i1) ? g1 : ((2 * tig     == i2) ? g2 : 0.f);
                gw[row * 8 + 2 * tig + 1] = (2 * tig + 1 == i1) ? g1 : ((2 * tig + 1 == i2) ? g2 : 0.f);
            }
        }
    }
    __syncthreads();

#pragma unroll
    for (int mt = 0; mt < 2; ++mt) {
#pragma unroll
        for (int nt = 0; nt < 8; ++nt) {
            const int col = ncol0 + nt * 8 + 2 * tig;
            const int e  = col >> 4;
            const int ra = wm * 32 + mt * 16 + g;
            const float wa = gw[ra * 8 + e];
            const float wb = gw[(ra + 8) * 8 + e];
            uint32_t w0 = pack_f16x2(acc[mt][nt][0] * wa, acc[mt][nt][1] * wa);
            uint32_t w1 = pack_f16x2(acc[mt][nt][2] * wb, acc[mt][nt][3] * wb);
            const int m16 = (m0 + wm * 32 + mt * 16) >> 4;
            const int k16 = wn * 4 + (nt >> 1);
            *(uint2*)(g_hwf + ((size_t)m16 * 8 + k16) * 128
                            + lane * 4 + 2 * (nt & 1)) = make_uint2(w0, w1);
        }
    }
}

// ============================================================================
// GEMM2: persistent grid-148. Tile space = 4096 tiles (nb 0..31 x mt 0..127),
// nb-major; CTA i owns tiles [i*4096/148, (i+1)*4096/148) -> 27-28 tiles,
// <=2 nb-segments. Per segment: B loaded once; A ring-3 with ONE syncthreads
// and ONE CP_WAIT(1) per tile (uniform one-commit-group-per-iter invariant).
// SMEM: B 32KB + 3x A 32KB = 128KB, 1 CTA/SM.
// ============================================================================
#define BS2_WORDS 8192
#define AS2_WORDS 8192
#define SM2_WORDS (BS2_WORDS + 3 * AS2_WORDS)   // 32768 words = 128 KB
#define NTILES2   4096
#define GRID2     148

__global__ __launch_bounds__(256, 1)
void gemm2_kernel(float* __restrict__ out)
{
    extern __shared__ uint32_t smu[];
    uint32_t* Bs = smu;
    uint32_t* As = smu + BS2_WORDS;

    const int tid  = threadIdx.x;
    const int lane = tid & 31;
    const int warp = tid >> 5;
    const int wm   = warp & 3;
    const int wn   = warp >> 2;

    auto issueA = [&](int buf, int tile) {
        const size_t src = (size_t)(tile & 127) * 8192;
        uint32_t* dst = As + buf * AS2_WORDS;
#pragma unroll
        for (int i = 0; i < 8; i++) {
            int idx = tid + i * 256;
            cp16(dst + idx * 4, g_hwf + src + idx * 4);
        }
    };

    int t0 = (int)(((long long)blockIdx.x * NTILES2) / GRID2);
    const int t1 = (int)(((long long)(blockIdx.x + 1) * NTILES2) / GRID2);

    while (t0 < t1) {
        const int nb   = t0 >> 7;
        const int send = min(t1, (nb + 1) << 7);
        const int ntl  = send - t0;
        const int n0   = nb * 128;

        __syncthreads();   // protect B (and A bufs) from overwrite across segments

        // group: B + A(t0) together
        {
            const size_t bo = (size_t)nb * 8192;
#pragma unroll
            for (int i = 0; i < 8; i++) {
                int idx = tid + i * 256;
                cp16(Bs + idx * 4, g_btf + bo + idx * 4);
            }
        }
        issueA(0, t0);
        CP_COMMIT();
        if (ntl > 1) issueA(1, t0 + 1);
        CP_COMMIT();       // group (A t0+1) — possibly empty

        for (int i = 0; i < ntl; ++i) {
            const int t = t0 + i;
            CP_WAIT(1);            // group for tile t (and B on i==0) landed
            __syncthreads();       // publish; also certifies compute(t-1) done
            if (i + 2 < ntl) issueA((i + 2) % 3, t + 2);
            CP_COMMIT();           // exactly one group per iteration

            const uint32_t* a = As + (i % 3) * AS2_WORDS;

            float acc[2][8][4];
#pragma unroll
            for (int mt = 0; mt < 2; mt++)
#pragma unroll
                for (int nt = 0; nt < 8; nt++)
#pragma unroll
                    for (int j = 0; j < 4; j++) acc[mt][nt][j] = 0.f;

#pragma unroll
            for (int ks = 0; ks < 8; ++ks) {
                uint4 af[2];
#pragma unroll
                for (int mt = 0; mt < 2; mt++)
                    af[mt] = *(const uint4*)(a + ((wm * 2 + mt) * 8 + ks) * 128 + lane * 4);
                uint2 bf[8];
#pragma unroll
                for (int nt = 0; nt < 8; nt++) {
                    const int n8l = wn * 8 + nt;
                    bf[nt] = *(const uint2*)(Bs + (n8l * 8 + ks) * 64 + lane * 2);
                }
#pragma unroll
                for (int nt = 0; nt < 8; nt++)
#pragma unroll
                    for (int mt = 0; mt < 2; mt++)
                        mma_f16(acc[mt][nt], (const uint32_t*)&af[mt], bf[nt].x, bf[nt].y);
            }

            {
                const int g   = lane >> 2;
                const int tig = lane & 3;
                const int mbase = (t & 127) * 128;
#pragma unroll
                for (int mt = 0; mt < 2; ++mt) {
#pragma unroll
                    for (int nt = 0; nt < 8; ++nt) {
                        const int col = n0 + wn * 64 + nt * 8 + 2 * tig;
                        const int ra  = mbase + wm * 32 + mt * 16 + g;
                        *(float2*)(out + (size_t)ra * OUT_D + col) =
                            make_float2(acc[mt][nt][0], acc[mt][nt][1]);
                        *(float2*)(out + (size_t)(ra + 8) * OUT_D + col) =
                            make_float2(acc[mt][nt][2], acc[mt][nt][3]);
                    }
                }
            }
        }
        t0 = send;
    }
}

// ============================================================================
extern "C" void kernel_launch(void* const* d_in, const int* in_sizes, int n_in,
                              void* d_out, int out_size)
{
    const float* x  = (const float*)d_in[0];   // [N, 4096]
    const float* rw = (const float*)d_in[1];   // [8, 4096]
    const float* rb = (const float*)d_in[2];   // [8]
    const float* A  = (const float*)d_in[3];   // [8,16,4096]
    const float* Bm = (const float*)d_in[4];   // [8,4096,16]
    float* out = (float*)d_out;                // [N, 4096] fp32

    const int sm1 = SM1_WORDS * 4;   // 212992 B
    const int sm2 = SM2_WORDS * 4;   // 131072 B
    cudaFuncSetAttribute(gemm1_kernel,
                         cudaFuncAttributeMaxDynamicSharedMemorySize, sm1);
    cudaFuncSetAttribute(gemm2_kernel,
                         cudaFuncAttributeMaxDynamicSharedMemorySize, sm2);

    prep_kernel<<<1024, 256>>>(rw, A, Bm);
    gemm1_kernel<<<N_TOK / 128, 256, sm1>>>(x, rb);
    gemm2_kernel<<<GRID2, 256, sm2>>>(out);
}

// round 14
// speedup vs baseline: 1.2783x; 1.0227x over previous
#include <cuda_runtime.h>
#include <cuda_fp16.h>
#include <cstdint>
#include <cstddef>

// Problem constants: B=4, S=4096 -> N=16384 tokens
#define N_TOK 16384
#define DIM   4096
#define OUT_D 4096
#define SCALING 0.5f
#define W1_N8 18   // 144 rows / 8: 16 A-blocks + router-hi + router-lo

// -------- static scratch, fp16 fragment-major (m16n8k16) --------
// GEMM1 B operand, interleaved per k32: [k32 0..127][n8 0..17][lane][4]
//   word = lane*4 + ks16*2 + reg; lane=(n&7)*4+((k&7)>>1), reg=(k>>3)&1
__device__ __align__(16) uint32_t g_w1f[128 * W1_N8 * 128];
// GEMM2 B operand: [n8 0..511][k16 0..7][lane*2 + reg]
__device__ __align__(16) uint32_t g_btf[512 * 8 * 64];
// GEMM2 A operand: [m16 0..1023][k16 0..7][lane*4 + reg]
__device__ __align__(16) uint32_t g_hwf[(size_t)1024 * 8 * 128];

// -------- helpers --------
__device__ __forceinline__ uint32_t pack_f16x2(float lo, float hi) {
    uint32_t r;   // d.low = 2nd src, d.high = 1st src
    asm("cvt.rn.f16x2.f32 %0, %1, %2;" : "=r"(r) : "f"(hi), "f"(lo));
    return r;
}
__device__ __forceinline__ float2 unpack_f16x2(uint32_t v) {
    __half2 h = *(__half2*)&v;
    return __half22float2(h);
}
__device__ __forceinline__ void mma_f16(float* c, const uint32_t* a,
                                        uint32_t b0, uint32_t b1) {
    asm volatile(
        "mma.sync.aligned.m16n8k16.row.col.f32.f16.f16.f32 "
        "{%0,%1,%2,%3}, {%4,%5,%6,%7}, {%8,%9}, {%0,%1,%2,%3};\n"
        : "+f"(c[0]), "+f"(c[1]), "+f"(c[2]), "+f"(c[3])
        : "r"(a[0]), "r"(a[1]), "r"(a[2]), "r"(a[3]), "r"(b0), "r"(b1));
}
__device__ __forceinline__ void cp16(void* dst, const void* src) {
    uint32_t d = (uint32_t)__cvta_generic_to_shared(dst);
    asm volatile("cp.async.cg.shared.global [%0], [%1], 16;" :: "r"(d), "l"(src));
}
#define CP_COMMIT() asm volatile("cp.async.commit_group;")
#define CP_WAIT(n)  asm volatile("cp.async.wait_group %0;" :: "n"(n))

// ============================================================================
// Prep: build fp16 fragment-major operand tensors once.
// ============================================================================
__global__ void prep_kernel(const float* __restrict__ rw,
                            const float* __restrict__ A,
                            const float* __restrict__ Bm)
{
    const int nthr = gridDim.x * blockDim.x;
    const int tid0 = blockIdx.x * blockDim.x + threadIdx.x;
    // W1: rows 0-127 A, 128-135 router hi, 136-143 router lo residual
    // Interleaved-per-k32 layout (validated in R9):
    for (int i = tid0; i < 144 * 2048; i += nthr) {
        int n = i >> 11, k = (i & 2047) * 2;
        float v0, v1;
        if (n < 128) {
            v0 = A[n * 4096 + k]; v1 = A[n * 4096 + k + 1];
        } else if (n < 136) {
            v0 = rw[(n - 128) * 4096 + k]; v1 = rw[(n - 128) * 4096 + k + 1];
        } else {
            float f0 = rw[(n - 136) * 4096 + k];
            float f1 = rw[(n - 136) * 4096 + k + 1];
            v0 = f0 - __half2float(__float2half_rn(f0));
            v1 = f1 - __half2float(__float2half_rn(f1));
        }
        int lane = (n & 7) * 4 + ((k & 7) >> 1);
        int idx = ((k >> 5) * W1_N8 + (n >> 3)) * 128
                + lane * 4 + ((k >> 4) & 1) * 2 + ((k >> 3) & 1);
        g_w1f[idx] = pack_f16x2(v0, v1);
    }
    for (int i = tid0; i < 4096 * 64; i += nthr) {
        int o = i >> 6, c = (i & 63) * 2;
        int e = c >> 4, r = c & 15;
        const float* bp = Bm + ((size_t)e * 4096 + o) * 16 + r;
        int idx = ((o >> 3) * 8 + (c >> 4)) * 64
                + ((o & 7) * 4 + ((c & 7) >> 1)) * 2 + ((c >> 3) & 1);
        g_btf[idx] = pack_f16x2(bp[0] * SCALING, bp[1] * SCALING);
    }
}

// ============================================================================
// GEMM1 (R12 structure: k64 stages, ring 4, 64 barriers) with hoisted
// uint4 B-fragment loads (half the B-LDS instructions per k32 tile).
// ============================================================================
#define AT_WORDS  (128 * 32)
#define AS_STAGE  (2 * AT_WORDS)
#define AS_WORDS  (4 * AS_STAGE)
#define WT_WORDS  (W1_N8 * 128)           // one k32 W slab: 2304 words
#define WS_STAGE  (2 * WT_WORDS)
#define WS_WORDS  (4 * WS_STAGE)
#define SM1_WORDS (AS_WORDS + WS_WORDS + 1024 + 1024)

__global__ __launch_bounds__(256, 1)
void gemm1_kernel(const float* __restrict__ x, const float* __restrict__ rb)
{
    extern __shared__ uint32_t smu[];
    uint32_t* As   = smu;
    uint32_t* Ws   = smu + AS_WORDS;
    float*    gw   = (float*)(smu + AS_WORDS + WS_WORDS);
    float*    lbuf = (float*)(smu + AS_WORDS + WS_WORDS + 1024);

    const int tid  = threadIdx.x;
    const int lane = tid & 31;
    const int warp = tid >> 5;
    const int wm   = warp & 3;
    const int wn   = warp >> 2;
    const int g    = lane >> 2;
    const int tig  = lane & 3;
    const int m0   = blockIdx.x * 128;
    const int ncol0 = wn * 64;

    float acc[2][9][4];
#pragma unroll
    for (int mt = 0; mt < 2; mt++)
#pragma unroll
        for (int nt = 0; nt < 9; nt++)
#pragma unroll
            for (int i = 0; i < 4; i++) acc[mt][nt][i] = 0.f;

    auto issue = [&](int stage, int u) {
        uint32_t* ab = As + stage * AS_STAGE;
        uint32_t* wb = Ws + stage * WS_STAGE;
#pragma unroll
        for (int sub = 0; sub < 2; ++sub) {
            const int t  = 2 * u + sub;
            const int k0 = t * 32;
            uint32_t* a = ab + sub * AT_WORDS;
            uint32_t* w = wb + sub * WT_WORDS;
#pragma unroll
            for (int i = 0; i < 4; i++) {
                int idx = tid + i * 256, row = idx >> 3, c4 = idx & 7;
                int col = (4 * c4) ^ ((row & 7) * 4);
                cp16(a + row * 32 + col, x + (size_t)(m0 + row) * DIM + k0 + 4 * c4);
            }
#pragma unroll
            for (int i = 0; i < 3; i++) {
                int idx = tid + i * 256;
                if (idx < 576)
                    cp16(w + idx * 4, g_w1f + (size_t)t * WT_WORDS + idx * 4);
            }
        }
    };

    issue(0, 0); CP_COMMIT();
    issue(1, 1); CP_COMMIT();
    issue(2, 2); CP_COMMIT();

    const int U = DIM / 64;
    for (int u = 0; u < U; ++u) {
        CP_WAIT(2);
        __syncthreads();
        if (u + 3 < U) issue((u + 3) & 3, u + 3);
        CP_COMMIT();

#pragma unroll
        for (int sub = 0; sub < 2; ++sub) {
            const int t = 2 * u + sub;
            const uint32_t* a = As + (u & 3) * AS_STAGE + sub * AT_WORDS;
            const uint32_t* w = Ws + (u & 3) * WS_STAGE + sub * WT_WORDS;
            const bool do_logits = (wn == (t & 1));

            // hoisted B fragments: one LDS.128 per n8 covers both k16 steps
            uint4 bb4[8];
#pragma unroll
            for (int nt = 0; nt < 8; ++nt)
                bb4[nt] = *(const uint4*)(w + (wn * 8 + nt) * 128 + lane * 4);
            uint4 bh4 = make_uint4(0, 0, 0, 0), bl4 = make_uint4(0, 0, 0, 0);
            if (do_logits) {
                bh4 = *(const uint4*)(w + 16 * 128 + lane * 4);
                bl4 = *(const uint4*)(w + 17 * 128 + lane * 4);
            }

#pragma unroll
            for (int ks = 0; ks < 2; ++ks) {
                const int k = ks * 16;
                uint32_t af[2][4];
                float2 raw[2][4];
#pragma unroll
                for (int mt = 0; mt < 2; ++mt) {
                    const int r0 = wm * 32 + mt * 16 + g;
                    const int clo = k + 2 * tig, chi = k + 8 + 2 * tig;
                    const int alo0 = r0 * 32 + (((clo & ~3) ^ ((r0 & 7) * 4)) | (clo & 3));
                    const int alo1 = (r0 + 8) * 32 + (((clo & ~3) ^ (((r0 + 8) & 7) * 4)) | (clo & 3));
                    const int ahi0 = r0 * 32 + (((chi & ~3) ^ ((r0 & 7) * 4)) | (chi & 3));
                    const int ahi1 = (r0 + 8) * 32 + (((chi & ~3) ^ (((r0 + 8) & 7) * 4)) | (chi & 3));
                    raw[mt][0] = *(const float2*)(a + alo0);
                    raw[mt][1] = *(const float2*)(a + alo1);
                    raw[mt][2] = *(const float2*)(a + ahi0);
                    raw[mt][3] = *(const float2*)(a + ahi1);
#pragma unroll
                    for (int j = 0; j < 4; j++)
                        af[mt][j] = pack_f16x2(raw[mt][j].x, raw[mt][j].y);
                }
#pragma unroll
                for (int nt = 0; nt < 8; ++nt) {
                    uint32_t b0 = ks ? bb4[nt].z : bb4[nt].x;
                    uint32_t b1 = ks ? bb4[nt].w : bb4[nt].y;
                    mma_f16(acc[0][nt], af[0], b0, b1);
                    mma_f16(acc[1][nt], af[1], b0, b1);
                }
                if (do_logits) {
                    uint32_t alo[2][4];
#pragma unroll
                    for (int mt = 0; mt < 2; ++mt)
#pragma unroll
                        for (int j = 0; j < 4; j++) {
                            float2 hv = unpack_f16x2(af[mt][j]);
                            alo[mt][j] = pack_f16x2(raw[mt][j].x - hv.x,
                                                    raw[mt][j].y - hv.y);
                        }
                    uint32_t h0 = ks ? bh4.z : bh4.x, h1 = ks ? bh4.w : bh4.y;
                    uint32_t l0 = ks ? bl4.z : bl4.x, l1 = ks ? bl4.w : bl4.y;
                    mma_f16(acc[0][8], af[0], h0, h1);
                    mma_f16(acc[1][8], af[1], h0, h1);
                    mma_f16(acc[0][8], af[0], l0, l1);
                    mma_f16(acc[1][8], af[1], l0, l1);
                    mma_f16(acc[0][8], alo[0], h0, h1);
                    mma_f16(acc[1][8], alo[1], h0, h1);
                }
            }
        }
    }

    if (wn == 0) {
#pragma unroll
        for (int mt = 0; mt < 2; ++mt)
#pragma unroll
            for (int j = 0; j < 4; ++j)
                lbuf[((wm * 2 + mt) * 32 + lane) * 4 + j] = acc[mt][8][j];
    }
    __syncthreads();

    if (wn == 1) {
        const float rb0 = rb[2 * tig];
        const float rb1 = rb[2 * tig + 1];
#pragma unroll
        for (int mt = 0; mt < 2; ++mt) {
#pragma unroll
            for (int j = 0; j < 4; ++j)
                acc[mt][8][j] += lbuf[((wm * 2 + mt) * 32 + lane) * 4 + j];
#pragma unroll
            for (int half = 0; half < 2; ++half) {
                float l0 = acc[mt][8][half * 2 + 0] + rb0;
                float l1 = acc[mt][8][half * 2 + 1] + rb1;
                float m1, m2; int i1, i2;
                if (l0 >= l1) { m1 = l0; i1 = 2 * tig;     m2 = l1; i2 = 2 * tig + 1; }
                else          { m1 = l1; i1 = 2 * tig + 1; m2 = l0; i2 = 2 * tig; }
#pragma unroll
                for (int d = 1; d <= 2; d <<= 1) {
                    float om1 = __shfl_xor_sync(0xffffffffu, m1, d);
                    int   oi1 = __shfl_xor_sync(0xffffffffu, i1, d);
                    float om2 = __shfl_xor_sync(0xffffffffu, m2, d);
                    int   oi2 = __shfl_xor_sync(0xffffffffu, i2, d);
                    if (om1 > m1) {
                        if (m1 >= om2) { m2 = m1; i2 = i1; }
                        else           { m2 = om2; i2 = oi2; }
                        m1 = om1; i1 = oi1;
                    } else if (om1 > m2) { m2 = om1; i2 = oi1; }
                }
                float g1 = 1.f / (1.f + __expf(m2 - m1));
                float g2 = 1.f - g1;
                int row = wm * 32 + mt * 16 + half * 8 + g;
                gw[row * 8 + 2 * tig]     = (2 * tig     == i1) ? g1 : ((2 * tig     == i2) ? g2 : 0.f);
                gw[row * 8 + 2 * tig + 1] = (2 * tig + 1 == i1) ? g1 : ((2 * tig + 1 == i2) ? g2 : 0.f);
            }
        }
    }
    __syncthreads();

#pragma unroll
    for (int mt = 0; mt < 2; ++mt) {
#pragma unroll
        for (int nt = 0; nt < 8; ++nt) {
            const int col = ncol0 + nt * 8 + 2 * tig;
            const int e  = col >> 4;
            const int ra = wm * 32 + mt * 16 + g;
            const float wa = gw[ra * 8 + e];
            const float wb = gw[(ra + 8) * 8 + e];
            uint32_t w0 = pack_f16x2(acc[mt][nt][0] * wa, acc[mt][nt][1] * wa);
            uint32_t w1 = pack_f16x2(acc[mt][nt][2] * wb, acc[mt][nt][3] * wb);
            const int m16 = (m0 + wm * 32 + mt * 16) >> 4;
            const int k16 = wn * 4 + (nt >> 1);
            *(uint2*)(g_hwf + ((size_t)m16 * 8 + k16) * 128
                            + lane * 4 + 2 * (nt & 1)) = make_uint2(w0, w1);
        }
    }
}

// ============================================================================
// GEMM2: persistent grid-148 over 2048 pair-tiles (nb 0..31 x mpair 0..63).
// Each iteration computes 256 rows (two 128-row tiles) against ONE B-frag
// load sweep: B-LDS per tile halves. Ring-2 A staging (two tiles = 64KB per
// stage), one commit-group per iteration. SMEM 32 + 2*64 = 160KB, 1 CTA/SM.
// ============================================================================
#define BS2_WORDS 8192
#define AP2_WORDS 16384                        // one stage = 2 m-tiles
#define SM2_WORDS (BS2_WORDS + 2 * AP2_WORDS)  // 40960 words = 160 KB
#define NPAIRS2   2048
#define GRID2     148

__global__ __launch_bounds__(256, 1)
void gemm2_kernel(float* __restrict__ out)
{
    extern __shared__ uint32_t smu[];
    uint32_t* Bs = smu;
    uint32_t* As = smu + BS2_WORDS;

    const int tid  = threadIdx.x;
    const int lane = tid & 31;
    const int warp = tid >> 5;
    const int wm   = warp & 3;
    const int wn   = warp >> 2;

    auto issueA = [&](int buf, int pt) {
        const size_t src = (size_t)(pt & 63) * 2 * 8192;   // two contiguous m-tiles
        uint32_t* dst = As + buf * AP2_WORDS;
#pragma unroll
        for (int i = 0; i < 16; i++) {
            int idx = tid + i * 256;
            cp16(dst + idx * 4, g_hwf + src + idx * 4);
        }
    };

    int p0 = (int)(((long long)blockIdx.x * NPAIRS2) / GRID2);
    const int p1 = (int)(((long long)(blockIdx.x + 1) * NPAIRS2) / GRID2);

    while (p0 < p1) {
        const int nb   = p0 >> 6;
        const int send = min(p1, (nb + 1) << 6);
        const int npl  = send - p0;
        const int n0   = nb * 128;

        __syncthreads();   // protect B/A buffers across segments

        {
            const size_t bo = (size_t)nb * 8192;
#pragma unroll
            for (int i = 0; i < 8; i++) {
                int idx = tid + i * 256;
                cp16(Bs + idx * 4, g_btf + bo + idx * 4);
            }
        }
        issueA(0, p0);
        CP_COMMIT();
        if (npl > 1) issueA(1, p0 + 1);
        CP_COMMIT();       // possibly empty group

        for (int i = 0; i < npl; ++i) {
            const int pt = p0 + i;
            CP_WAIT(1);            // group for pair pt (and B on i==0) landed
            __syncthreads();

            const uint32_t* a0 = As + (i & 1) * AP2_WORDS;
            const uint32_t* a1 = a0 + 8192;

            float acc[4][8][4];    // [tile*2+mt][nt][4]
#pragma unroll
            for (int q = 0; q < 4; q++)
#pragma unroll
                for (int nt = 0; nt < 8; nt++)
#pragma unroll
                    for (int j = 0; j < 4; j++) acc[q][nt][j] = 0.f;

#pragma unroll
            for (int ks = 0; ks < 8; ++ks) {
                uint4 af[4];
#pragma unroll
                for (int mt = 0; mt < 2; mt++) {
                    af[mt]     = *(const uint4*)(a0 + ((wm * 2 + mt) * 8 + ks) * 128 + lane * 4);
                    af[2 + mt] = *(const uint4*)(a1 + ((wm * 2 + mt) * 8 + ks) * 128 + lane * 4);
                }
                uint2 bf[8];
#pragma unroll
                for (int nt = 0; nt < 8; nt++) {
                    const int n8l = wn * 8 + nt;
                    bf[nt] = *(const uint2*)(Bs + (n8l * 8 + ks) * 64 + lane * 2);
                }
#pragma unroll
                for (int nt = 0; nt < 8; nt++)
#pragma unroll
                    for (int q = 0; q < 4; q++)
                        mma_f16(acc[q][nt], (const uint32_t*)&af[q], bf[nt].x, bf[nt].y);
            }

            {
                const int g   = lane >> 2;
                const int tig = lane & 3;
#pragma unroll
                for (int tile = 0; tile < 2; ++tile) {
                    const int mbase = ((pt & 63) * 2 + tile) * 128;
#pragma unroll
                    for (int mt = 0; mt < 2; ++mt) {
#pragma unroll
                        for (int nt = 0; nt < 8; ++nt) {
                            const int col = n0 + wn * 64 + nt * 8 + 2 * tig;
                            const int ra  = mbase + wm * 32 + mt * 16 + g;
                            const float* av = acc[tile * 2 + mt][nt];
                            *(float2*)(out + (size_t)ra * OUT_D + col) =
                                make_float2(av[0], av[1]);
                            *(float2*)(out + (size_t)(ra + 8) * OUT_D + col) =
                                make_float2(av[2], av[3]);
                        }
                    }
                }
            }

            __syncthreads();       // all warps done with buffer i&1
            if (i + 2 < npl) issueA(i & 1, pt + 2);
            CP_COMMIT();           // exactly one group per iteration
        }
        p0 = send;
    }
}

// ============================================================================
extern "C" void kernel_launch(void* const* d_in, const int* in_sizes, int n_in,
                              void* d_out, int out_size)
{
    const float* x  = (const float*)d_in[0];   // [N, 4096]
    const float* rw = (const float*)d_in[1];   // [8, 4096]
    const float* rb = (const float*)d_in[2];   // [8]
    const float* A  = (const float*)d_in[3];   // [8,16,4096]
    const float* Bm = (const float*)d_in[4];   // [8,4096,16]
    float* out = (float*)d_out;                // [N, 4096] fp32

    const int sm1 = SM1_WORDS * 4;   // 212992 B
    const int sm2 = SM2_WORDS * 4;   // 163840 B
    cudaFuncSetAttribute(gemm1_kernel,
                         cudaFuncAttributeMaxDynamicSharedMemorySize, sm1);
    cudaFuncSetAttribute(gemm2_kernel,
                         cudaFuncAttributeMaxDynamicSharedMemorySize, sm2);

    prep_kernel<<<1024, 256>>>(rw, A, Bm);
    gemm1_kernel<<<N_TOK / 128, 256, sm1>>>(x, rb);
    gemm2_kernel<<<GRID2, 256, sm2>>>(out);
}